// round 16
// baseline (speedup 1.0000x reference)
#include <cuda_runtime.h>
#include <cstdint>

#define D 128
#define KH 8
#define MAXN 100000
#define TILE_NODES 64

// ---------------- persistent device scratch (no allocations allowed) ----------
__device__ float d_s1[MAXN * KH];          // s1[n,k] = relu(x[n]@Ww_k)@Wm_k (only for mask bits set)
__device__ float d_acc[MAXN * KH];         // edge-aggregated scalar scores
__device__ unsigned char d_mbits[MAXN];    // packed per-node mask bits
__device__ int d_list[KH * MAXN];          // per-head compacted node lists
__device__ int d_counts[KH * 64];          // padded counters (256B apart -> distinct LTS)

// ---------------- kernel 0: zero the per-head counters -----------------------
__global__ void k_zero_counts() {
    if (threadIdx.x < KH) d_counts[threadIdx.x * 64] = 0;
}

// ---------------- kernel 1: build mask bits, zero acc, compact node lists ----
__global__ void k_build(const float* __restrict__ mask, int N) {
    int n = blockIdx.x * blockDim.x + threadIdx.x;
    bool valid = (n < N);
    unsigned int bits = 0;
    if (valid) {
        const float4* m4 = (const float4*)mask;
        float4 a = m4[n * 2 + 0];
        float4 b = m4[n * 2 + 1];
        bits |= (a.x > 0.f) ? 1u   : 0u;
        bits |= (a.y > 0.f) ? 2u   : 0u;
        bits |= (a.z > 0.f) ? 4u   : 0u;
        bits |= (a.w > 0.f) ? 8u   : 0u;
        bits |= (b.x > 0.f) ? 16u  : 0u;
        bits |= (b.y > 0.f) ? 32u  : 0u;
        bits |= (b.z > 0.f) ? 64u  : 0u;
        bits |= (b.w > 0.f) ? 128u : 0u;
        d_mbits[n] = (unsigned char)bits;
        float4 z = make_float4(0.f, 0.f, 0.f, 0.f);
        ((float4*)d_acc)[n * 2 + 0] = z;
        ((float4*)d_acc)[n * 2 + 1] = z;
    }
    int lane = threadIdx.x & 31;
    #pragma unroll
    for (int i = 0; i < KH; i++) {
        bool pred = valid && ((bits >> i) & 1u);
        unsigned int ball = __ballot_sync(0xffffffffu, pred);
        if (ball) {
            int leader = __ffs(ball) - 1;
            int base = 0;
            if (lane == leader) base = atomicAdd(&d_counts[i * 64], __popc(ball));
            base = __shfl_sync(0xffffffffu, base, leader);
            if (pred) {
                int pos = base + __popc(ball & ((1u << lane) - 1u));
                d_list[i * MAXN + pos] = n;
            }
        }
    }
}

// ---------------- kernel 2: compacted GEMM + fused relu + Wm-reduce ----------
// Per CTA: one head, 64 (compacted) nodes, full 128 output cols.
// smem: Xs[64][128] + Ws[128][128] + nidx[64]  = 96.25 KB dynamic -> 2 CTA/SM.
// Thread map: cg = tid&15 owns cols {cg*4..+3} U {64+cg*4..+3} (bank-conflict-free
// LDS.128 phases); ng = tid>>4 owns 4 nodes. 32 fp32 accumulators / thread.
extern __shared__ float smem_dyn[];

__global__ __launch_bounds__(256) void k_gemm(const float* __restrict__ x,
                                              const float* __restrict__ Ww,
                                              const float* __restrict__ Wm) {
    int head = blockIdx.y;
    int cnt = d_counts[head * 64];
    int tile0 = blockIdx.x * TILE_NODES;
    if (tile0 >= cnt) return;

    float* Xs = smem_dyn;                       // 64*128 floats
    float* Ws = smem_dyn + TILE_NODES * D;      // 128*128 floats
    int*  nidx = (int*)(Ws + D * D);            // 64 ints

    int tid = threadIdx.x;
    if (tid < TILE_NODES) {
        int p = tile0 + tid;
        nidx[tid] = d_list[head * MAXN + (p < cnt ? p : cnt - 1)];
    }
    __syncthreads();

    // gather X rows (each row is a contiguous 512B segment -> coalesced)
    const float4* x4 = (const float4*)x;
    float4* Xs4 = (float4*)Xs;
    for (int i = tid; i < TILE_NODES * (D / 4); i += 256) {
        int r = i >> 5;
        int c = i & 31;
        Xs4[i] = x4[nidx[r] * (D / 4) + c];
    }
    // stream full Ww head into smem
    const float4* w4 = (const float4*)(Ww + head * D * D);
    float4* Ws4 = (float4*)Ws;
    for (int i = tid; i < D * (D / 4); i += 256) Ws4[i] = w4[i];
    __syncthreads();

    int cg = tid & 15;
    int ng = tid >> 4;
    int colA = cg * 4;
    int colB = 64 + cg * 4;
    int node0 = ng * 4;

    float acc[4][8];
    #pragma unroll
    for (int j = 0; j < 4; j++)
        #pragma unroll
        for (int c = 0; c < 8; c++) acc[j][c] = 0.f;

    #pragma unroll 1
    for (int k = 0; k < D; k += 4) {
        float4 xa[4];
        #pragma unroll
        for (int j = 0; j < 4; j++)
            xa[j] = *(const float4*)&Xs[(node0 + j) * D + k];
        #pragma unroll
        for (int kk = 0; kk < 4; kk++) {
            float4 wa = *(const float4*)&Ws[(k + kk) * D + colA];
            float4 wb = *(const float4*)&Ws[(k + kk) * D + colB];
            #pragma unroll
            for (int j = 0; j < 4; j++) {
                float xv = (kk == 0) ? xa[j].x : (kk == 1) ? xa[j].y
                         : (kk == 2) ? xa[j].z : xa[j].w;
                acc[j][0] = fmaf(xv, wa.x, acc[j][0]);
                acc[j][1] = fmaf(xv, wa.y, acc[j][1]);
                acc[j][2] = fmaf(xv, wa.z, acc[j][2]);
                acc[j][3] = fmaf(xv, wa.w, acc[j][3]);
                acc[j][4] = fmaf(xv, wb.x, acc[j][4]);
                acc[j][5] = fmaf(xv, wb.y, acc[j][5]);
                acc[j][6] = fmaf(xv, wb.z, acc[j][6]);
                acc[j][7] = fmaf(xv, wb.w, acc[j][7]);
            }
        }
    }

    // epilogue: relu, dot with Wm cols, reduce across the 16 col-threads
    const float* wm = Wm + head * D;
    float wmv[8];
    wmv[0] = wm[colA];     wmv[1] = wm[colA + 1];
    wmv[2] = wm[colA + 2]; wmv[3] = wm[colA + 3];
    wmv[4] = wm[colB];     wmv[5] = wm[colB + 1];
    wmv[6] = wm[colB + 2]; wmv[7] = wm[colB + 3];

    #pragma unroll
    for (int j = 0; j < 4; j++) {
        float t = 0.f;
        #pragma unroll
        for (int c = 0; c < 8; c++)
            t = fmaf(fmaxf(acc[j][c], 0.f), wmv[c], t);
        #pragma unroll
        for (int off = 8; off >= 1; off >>= 1)
            t += __shfl_xor_sync(0xffffffffu, t, off, 16);
        if (cg == 0) {
            int p = tile0 + node0 + j;
            if (p < cnt)
                d_s1[nidx[node0 + j] * KH + head] = t;
        }
    }
}

// ---------------- kernel 3: scalar edge scatter (edge_index is INT32) ---------
// JAX default config has x64 disabled: the reference's jnp.int64 edge_index is
// silently downcast to int32 before it ever reaches the harness.
__global__ void k_edges(const int* __restrict__ ei, int E, int N) {
    int e = blockIdx.x * blockDim.x + threadIdx.x;
    if (e >= E) return;
    int src = ei[e];
    int dst = ei[E + e];
    // cheap insurance: never fault even if dtype assumptions are wrong
    if ((unsigned)src >= (unsigned)N || (unsigned)dst >= (unsigned)N) return;
    unsigned int common = (unsigned int)d_mbits[src] & (unsigned int)d_mbits[dst];
    if (!common) return;
    const float* srow = d_s1 + src * KH;
    float* arow = d_acc + dst * KH;
    do {
        int i = __ffs(common) - 1;
        common &= (common - 1u);
        atomicAdd(arow + i, __ldg(srow + i));
    } while (common);
}

// ---------------- kernel 4: score + top-2 combine (warp per node) -------------
__global__ void k_combine(const float* __restrict__ x, const float* __restrict__ Wm,
                          float* __restrict__ out, int N) {
    __shared__ float wm_s[KH * D];
    for (int i = threadIdx.x; i < KH * D; i += blockDim.x) wm_s[i] = Wm[i];
    __syncthreads();
    int gwarp = (int)((blockIdx.x * blockDim.x + threadIdx.x) >> 5);
    int lane = threadIdx.x & 31;
    if (gwarp >= N) return;
    int n = gwarp;

    float4 xv = ((const float4*)x)[n * (D / 4) + lane];
    unsigned int bits = d_mbits[n];           // uniform across warp
    unsigned int hbits = 0;
    for (unsigned int b = bits; b; b &= (b - 1u)) {
        int i = __ffs(b) - 1;
        float4 wv = ((const float4*)(wm_s + i * D))[lane];
        float p = xv.x * wv.x + xv.y * wv.y + xv.z * wv.z + xv.w * wv.w;
        #pragma unroll
        for (int off = 16; off >= 1; off >>= 1)
            p += __shfl_xor_sync(0xffffffffu, p, off);
        float score = p + d_acc[n * KH + i];  // broadcast load
        if (score > 0.f) hbits |= (1u << i);  // tanh(s)>0 <=> s>0
    }
    // lax.top_k tie-break = lowest index first; all candidate values equal ||x[n]||
    // => final mask = first min(2, popc) true heads.
    unsigned int l1 = hbits & (0u - hbits);
    unsigned int rem = hbits ^ l1;
    unsigned int l2 = rem & (0u - rem);
    unsigned int sel = l1 | l2;
    if (lane < KH)
        out[n * KH + lane] = ((sel >> lane) & 1u) ? 1.0f : 0.0f;
}

// ---------------- launch ------------------------------------------------------
extern "C" void kernel_launch(void* const* d_in, const int* in_sizes, int n_in,
                              void* d_out, int out_size) {
    const float* x    = (const float*)d_in[0];
    const int*   ei   = (const int*)d_in[1];    // int32 (JAX x64 disabled)
    const float* mask = (const float*)d_in[2];
    const float* Ww   = (const float*)d_in[3];
    const float* Wm   = (const float*)d_in[4];
    float* out = (float*)d_out;

    int N = in_sizes[2] / KH;     // 100000
    int E = in_sizes[1] / 2;      // 3200000

    k_zero_counts<<<1, 32>>>();
    k_build<<<(N + 255) / 256, 256>>>(mask, N);

    size_t smem = (size_t)(TILE_NODES * D + D * D) * sizeof(float)
                + TILE_NODES * sizeof(int);
    cudaFuncSetAttribute(k_gemm, cudaFuncAttributeMaxDynamicSharedMemorySize, (int)smem);
    dim3 grid((N + TILE_NODES - 1) / TILE_NODES, KH);
    k_gemm<<<grid, 256, smem>>>(x, Ww, Wm);

    k_edges<<<(E + 255) / 256, 256>>>(ei, E, N);

    k_combine<<<(N + 7) / 8, 256>>>(x, Wm, out, N);
}

// round 17
// speedup vs baseline: 1.0035x; 1.0035x over previous
#include <cuda_runtime.h>
#include <cstdint>

#define D 128
#define KH 8
#define MAXN 100000
#define TILE_NODES 64

// ---------------- persistent device scratch (no allocations allowed) ----------
__device__ float d_s1[MAXN * KH];          // s1[n,k] = relu(x[n]@Ww_k)@Wm_k (only for mask bits set)
__device__ float d_acc[MAXN * KH];         // edge-aggregated scalar scores
__device__ unsigned char d_mbits[MAXN];    // packed per-node mask bits
__device__ int d_list[KH * MAXN];          // per-head compacted node lists
__device__ int d_counts[KH * 64];          // padded counters (256B apart -> distinct LTS)

// ---------------- kernel 0: zero the per-head counters -----------------------
__global__ void k_zero_counts() {
    if (threadIdx.x < KH) d_counts[threadIdx.x * 64] = 0;
}

// ---------------- kernel 1: build mask bits, zero acc, compact node lists ----
__global__ void k_build(const float* __restrict__ mask, int N) {
    int n = blockIdx.x * blockDim.x + threadIdx.x;
    bool valid = (n < N);
    unsigned int bits = 0;
    if (valid) {
        const float4* m4 = (const float4*)mask;
        float4 a = m4[n * 2 + 0];
        float4 b = m4[n * 2 + 1];
        bits |= (a.x > 0.f) ? 1u   : 0u;
        bits |= (a.y > 0.f) ? 2u   : 0u;
        bits |= (a.z > 0.f) ? 4u   : 0u;
        bits |= (a.w > 0.f) ? 8u   : 0u;
        bits |= (b.x > 0.f) ? 16u  : 0u;
        bits |= (b.y > 0.f) ? 32u  : 0u;
        bits |= (b.z > 0.f) ? 64u  : 0u;
        bits |= (b.w > 0.f) ? 128u : 0u;
        d_mbits[n] = (unsigned char)bits;
        float4 z = make_float4(0.f, 0.f, 0.f, 0.f);
        ((float4*)d_acc)[n * 2 + 0] = z;
        ((float4*)d_acc)[n * 2 + 1] = z;
    }
    int lane = threadIdx.x & 31;
    #pragma unroll
    for (int i = 0; i < KH; i++) {
        bool pred = valid && ((bits >> i) & 1u);
        unsigned int ball = __ballot_sync(0xffffffffu, pred);
        if (ball) {
            int leader = __ffs(ball) - 1;
            int base = 0;
            if (lane == leader) base = atomicAdd(&d_counts[i * 64], __popc(ball));
            base = __shfl_sync(0xffffffffu, base, leader);
            if (pred) {
                int pos = base + __popc(ball & ((1u << lane) - 1u));
                d_list[i * MAXN + pos] = n;
            }
        }
    }
}

// ---------------- kernel 2: compacted GEMM + fused relu + Wm-reduce ----------
// Per CTA: one head, 64 (compacted) nodes, full 128 output cols.
// smem: Xs[64][128] + Ws[128][128] + nidx[64]  = 96.25 KB dynamic -> 2 CTA/SM.
// Thread map: cg = tid&15 owns cols {cg*4..+3} U {64+cg*4..+3} (bank-conflict-free
// LDS.128 phases); ng = tid>>4 owns 4 nodes. 32 fp32 accumulators / thread.
extern __shared__ float smem_dyn[];

__global__ __launch_bounds__(256) void k_gemm(const float* __restrict__ x,
                                              const float* __restrict__ Ww,
                                              const float* __restrict__ Wm) {
    int head = blockIdx.y;
    int cnt = d_counts[head * 64];
    int tile0 = blockIdx.x * TILE_NODES;
    if (tile0 >= cnt) return;

    float* Xs = smem_dyn;                       // 64*128 floats
    float* Ws = smem_dyn + TILE_NODES * D;      // 128*128 floats
    int*  nidx = (int*)(Ws + D * D);            // 64 ints

    int tid = threadIdx.x;
    if (tid < TILE_NODES) {
        int p = tile0 + tid;
        nidx[tid] = d_list[head * MAXN + (p < cnt ? p : cnt - 1)];
    }
    __syncthreads();

    // gather X rows (each row is a contiguous 512B segment -> coalesced)
    const float4* x4 = (const float4*)x;
    float4* Xs4 = (float4*)Xs;
    for (int i = tid; i < TILE_NODES * (D / 4); i += 256) {
        int r = i >> 5;
        int c = i & 31;
        Xs4[i] = x4[nidx[r] * (D / 4) + c];
    }
    // stream full Ww head into smem
    const float4* w4 = (const float4*)(Ww + head * D * D);
    float4* Ws4 = (float4*)Ws;
    for (int i = tid; i < D * (D / 4); i += 256) Ws4[i] = w4[i];
    __syncthreads();

    int cg = tid & 15;
    int ng = tid >> 4;
    int colA = cg * 4;
    int colB = 64 + cg * 4;
    int node0 = ng * 4;

    float acc[4][8];
    #pragma unroll
    for (int j = 0; j < 4; j++)
        #pragma unroll
        for (int c = 0; c < 8; c++) acc[j][c] = 0.f;

    #pragma unroll 1
    for (int k = 0; k < D; k += 4) {
        float4 xa[4];
        #pragma unroll
        for (int j = 0; j < 4; j++)
            xa[j] = *(const float4*)&Xs[(node0 + j) * D + k];
        #pragma unroll
        for (int kk = 0; kk < 4; kk++) {
            float4 wa = *(const float4*)&Ws[(k + kk) * D + colA];
            float4 wb = *(const float4*)&Ws[(k + kk) * D + colB];
            #pragma unroll
            for (int j = 0; j < 4; j++) {
                float xv = (kk == 0) ? xa[j].x : (kk == 1) ? xa[j].y
                         : (kk == 2) ? xa[j].z : xa[j].w;
                acc[j][0] = fmaf(xv, wa.x, acc[j][0]);
                acc[j][1] = fmaf(xv, wa.y, acc[j][1]);
                acc[j][2] = fmaf(xv, wa.z, acc[j][2]);
                acc[j][3] = fmaf(xv, wa.w, acc[j][3]);
                acc[j][4] = fmaf(xv, wb.x, acc[j][4]);
                acc[j][5] = fmaf(xv, wb.y, acc[j][5]);
                acc[j][6] = fmaf(xv, wb.z, acc[j][6]);
                acc[j][7] = fmaf(xv, wb.w, acc[j][7]);
            }
        }
    }

    // epilogue: relu, dot with Wm cols, reduce across the 16 col-threads
    const float* wm = Wm + head * D;
    float wmv[8];
    wmv[0] = wm[colA];     wmv[1] = wm[colA + 1];
    wmv[2] = wm[colA + 2]; wmv[3] = wm[colA + 3];
    wmv[4] = wm[colB];     wmv[5] = wm[colB + 1];
    wmv[6] = wm[colB + 2]; wmv[7] = wm[colB + 3];

    #pragma unroll
    for (int j = 0; j < 4; j++) {
        float t = 0.f;
        #pragma unroll
        for (int c = 0; c < 8; c++)
            t = fmaf(fmaxf(acc[j][c], 0.f), wmv[c], t);
        #pragma unroll
        for (int off = 8; off >= 1; off >>= 1)
            t += __shfl_xor_sync(0xffffffffu, t, off, 16);
        if (cg == 0) {
            int p = tile0 + node0 + j;
            if (p < cnt)
                d_s1[nidx[node0 + j] * KH + head] = t;
        }
    }
}

// ---------------- kernel 3: scalar edge scatter (edge_index is INT32) ---------
// JAX default config has x64 disabled: the reference's jnp.int64 edge_index is
// silently downcast to int32 before it ever reaches the harness.
__global__ void k_edges(const int* __restrict__ ei, int E, int N) {
    int e = blockIdx.x * blockDim.x + threadIdx.x;
    if (e >= E) return;
    int src = ei[e];
    int dst = ei[E + e];
    // cheap insurance: never fault even if dtype assumptions are wrong
    if ((unsigned)src >= (unsigned)N || (unsigned)dst >= (unsigned)N) return;
    unsigned int common = (unsigned int)d_mbits[src] & (unsigned int)d_mbits[dst];
    if (!common) return;
    const float* srow = d_s1 + src * KH;
    float* arow = d_acc + dst * KH;
    do {
        int i = __ffs(common) - 1;
        common &= (common - 1u);
        atomicAdd(arow + i, __ldg(srow + i));
    } while (common);
}

// ---------------- kernel 4: score + top-2 combine (warp per node) -------------
__global__ void k_combine(const float* __restrict__ x, const float* __restrict__ Wm,
                          float* __restrict__ out, int N) {
    __shared__ float wm_s[KH * D];
    for (int i = threadIdx.x; i < KH * D; i += blockDim.x) wm_s[i] = Wm[i];
    __syncthreads();
    int gwarp = (int)((blockIdx.x * blockDim.x + threadIdx.x) >> 5);
    int lane = threadIdx.x & 31;
    if (gwarp >= N) return;
    int n = gwarp;

    float4 xv = ((const float4*)x)[n * (D / 4) + lane];
    unsigned int bits = d_mbits[n];           // uniform across warp
    unsigned int hbits = 0;
    for (unsigned int b = bits; b; b &= (b - 1u)) {
        int i = __ffs(b) - 1;
        float4 wv = ((const float4*)(wm_s + i * D))[lane];
        float p = xv.x * wv.x + xv.y * wv.y + xv.z * wv.z + xv.w * wv.w;
        #pragma unroll
        for (int off = 16; off >= 1; off >>= 1)
            p += __shfl_xor_sync(0xffffffffu, p, off);
        float score = p + d_acc[n * KH + i];  // broadcast load
        if (score > 0.f) hbits |= (1u << i);  // tanh(s)>0 <=> s>0
    }
    // lax.top_k tie-break = lowest index first; all candidate values equal ||x[n]||
    // => final mask = first min(2, popc) true heads.
    unsigned int l1 = hbits & (0u - hbits);
    unsigned int rem = hbits ^ l1;
    unsigned int l2 = rem & (0u - rem);
    unsigned int sel = l1 | l2;
    if (lane < KH)
        out[n * KH + lane] = ((sel >> lane) & 1u) ? 1.0f : 0.0f;
}

// ---------------- launch ------------------------------------------------------
extern "C" void kernel_launch(void* const* d_in, const int* in_sizes, int n_in,
                              void* d_out, int out_size) {
    const float* x    = (const float*)d_in[0];
    const int*   ei   = (const int*)d_in[1];    // int32 (JAX x64 disabled)
    const float* mask = (const float*)d_in[2];
    const float* Ww   = (const float*)d_in[3];
    const float* Wm   = (const float*)d_in[4];
    float* out = (float*)d_out;

    int N = in_sizes[2] / KH;     // 100000
    int E = in_sizes[1] / 2;      // 3200000

    k_zero_counts<<<1, 32>>>();
    k_build<<<(N + 255) / 256, 256>>>(mask, N);

    size_t smem = (size_t)(TILE_NODES * D + D * D) * sizeof(float)
                + TILE_NODES * sizeof(int);
    cudaFuncSetAttribute(k_gemm, cudaFuncAttributeMaxDynamicSharedMemorySize, (int)smem);
    dim3 grid((N + TILE_NODES - 1) / TILE_NODES, KH);
    k_gemm<<<grid, 256, smem>>>(x, Ww, Wm);

    k_edges<<<(E + 255) / 256, 256>>>(ei, E, N);

    k_combine<<<(N + 7) / 8, 256>>>(x, Wm, out, N);
}